// round 11
// baseline (speedup 1.0000x reference)
#include <cuda_runtime.h>
#include <cstdint>

#define SLEN    2048
#define DHEAD   64
#define BHN     64
#define TQ      128
#define TK      64
#define NTHREADS 256
#define NKT     (SLEN / TK)
#define OUT_ELEMS ((size_t)BHN * SLEN * DHEAD)   // 8,388,608

#define PB      320                     // K & VT pitch bytes (80 words; LDS.128 conflict-free)
#define PITCHS  272                     // V stage pitch bytes
#define KBUF    (64 * PB)               // 20480
#define VSBUF   (64 * PITCHS)           // 17408

// ---- dynamic smem layout (bytes) ----
#define OFF_K0  0
#define OFF_K1  20480
#define OFF_VS  40960
#define OFF_VT  58368
#define OFF_BM  78848                   // 128 rows x 68 words = 34816
#define OFF_RS  113664
#define SMEM_BYTES (OFF_RS + 512)       // 114176 -> 2 CTAs/SM
#define BM_STRIDE 68

static __device__ __forceinline__ uint32_t smem_u32(const void* p) {
    uint32_t a;
    asm("{ .reg .u64 t; cvta.to.shared.u64 t, %1; cvt.u32.u64 %0, t; }" : "=r"(a) : "l"(p));
    return a;
}
static __device__ __forceinline__ void cp16(uint32_t sm, const void* g) {
    asm volatile("cp.async.cg.shared.global [%0], [%1], 16;" :: "r"(sm), "l"(g));
}
static __device__ __forceinline__ uint32_t f2tf(float f) {
    uint32_t u;
    asm("cvt.rna.tf32.f32 %0, %1;" : "=r"(u) : "f"(f));
    return u;
}
static __device__ __forceinline__ void mma_tf32(float* c, const uint32_t* a,
                                                uint32_t b0, uint32_t b1) {
    asm volatile("mma.sync.aligned.m16n8k8.row.col.f32.tf32.tf32.f32 "
                 "{%0,%1,%2,%3}, {%4,%5,%6,%7}, {%8,%9}, {%0,%1,%2,%3};"
                 : "+f"(c[0]), "+f"(c[1]), "+f"(c[2]), "+f"(c[3])
                 : "r"(a[0]), "r"(a[1]), "r"(a[2]), "r"(a[3]), "r"(b0), "r"(b1));
}
static __device__ __forceinline__ void lds128(uint32_t& a, uint32_t& b,
                                              uint32_t& c, uint32_t& d, uint32_t addr) {
    asm volatile("ld.shared.v4.b32 {%0,%1,%2,%3}, [%4];"
                 : "=r"(a), "=r"(b), "=r"(c), "=r"(d) : "r"(addr));
}

__global__ void __launch_bounds__(NTHREADS, 2)
sdpa_tf32_kernel(const float* __restrict__ Qg_all,
                 const float* __restrict__ Kg_all,
                 const float* __restrict__ Vg_all,
                 const int*   __restrict__ Mg_all,
                 float* __restrict__ Og_all,
                 float* __restrict__ Ag_all)
{
    extern __shared__ uint8_t smem[];
    const uint32_t smb = smem_u32(smem);
    uint32_t* BMw = (uint32_t*)(smem + OFF_BM);
    float* rowsum = (float*)(smem + OFF_RS);

    const int tid = threadIdx.x;
    const int w   = tid >> 5;
    const int l   = tid & 31;
    const int bh  = blockIdx.y;
    const int q0  = blockIdx.x * TQ;

    const float* Qg = Qg_all + (size_t)bh * SLEN * DHEAD;
    const float* Kg = Kg_all + (size_t)bh * SLEN * DHEAD;
    const float* Vg = Vg_all + (size_t)bh * SLEN * DHEAD;
    const int*   Mg = Mg_all + (size_t)bh * SLEN * SLEN;
    float*       Og = Og_all + (size_t)bh * SLEN * DHEAD;
    float*       Ag = Ag_all + (size_t)bh * SLEN * SLEN;

    auto issue_k = [&](int kt, int b) {
        if (kt < NKT) {
            const float* Kt = Kg + (size_t)kt * TK * DHEAD;
            const uint32_t base = smb + OFF_K0 + b * KBUF;
#pragma unroll
            for (int j = 0; j < 4; ++j) {
                const int idx = tid + j * NTHREADS;
                const int row = idx >> 4, ch = idx & 15;
                cp16(base + row * PB + ch * 16, Kt + row * DHEAD + ch * 4);
            }
        }
        asm volatile("cp.async.commit_group;" ::: "memory");
    };
    auto issue_v = [&](int kt) {
        if (kt < NKT) {
            const float* Vt = Vg + (size_t)kt * TK * DHEAD;
            const uint32_t base = smb + OFF_VS;
#pragma unroll
            for (int j = 0; j < 4; ++j) {
                const int idx = tid + j * NTHREADS;
                const int row = idx >> 4, ch = idx & 15;
                cp16(base + row * PITCHS + ch * 16, Vt + row * DHEAD + ch * 4);
            }
        }
        asm volatile("cp.async.commit_group;" ::: "memory");
    };
    // K stage: in-place RNA tf32 (1280 float4 incl. pads -> exactly 5/thread)
    auto sweep_k = [&](int b) {
        const uint32_t a0 = smb + OFF_K0 + b * KBUF + tid * 16;
#pragma unroll
        for (int j = 0; j < 5; ++j) {
            const uint32_t ad = a0 + j * (NTHREADS * 16);
            uint32_t x, y, z, t;
            asm volatile("ld.shared.v4.b32 {%0,%1,%2,%3}, [%4];"
                         : "=r"(x), "=r"(y), "=r"(z), "=r"(t) : "r"(ad));
            x = f2tf(__uint_as_float(x)); y = f2tf(__uint_as_float(y));
            z = f2tf(__uint_as_float(z)); t = f2tf(__uint_as_float(t));
            asm volatile("st.shared.v4.b32 [%0], {%1,%2,%3,%4};"
                         :: "r"(ad), "r"(x), "r"(y), "r"(z), "r"(t));
        }
    };
    // VS [k][d] -> VT [d][p(k)] with f2tf; p(k) = bit-shuffle so LDS.128 matches pp frags
    auto transpose_v = [&]() {
#pragma unroll
        for (int j = 0; j < 4; ++j) {
            const int idx = tid + j * NTHREADS;
            const int k = idx & 63, dc = idx >> 6;       // dc 0..15
            const int p = (k & 48) | (((k >> 1) & 3) << 2) | (((k >> 3) & 1) << 1) | (k & 1);
            const uint32_t sa = smb + OFF_VS + k * PITCHS + dc * 16;
            uint32_t x, y, z, t;
            asm volatile("ld.shared.v4.b32 {%0,%1,%2,%3}, [%4];"
                         : "=r"(x), "=r"(y), "=r"(z), "=r"(t) : "r"(sa));
            x = f2tf(__uint_as_float(x)); y = f2tf(__uint_as_float(y));
            z = f2tf(__uint_as_float(z)); t = f2tf(__uint_as_float(t));
            const uint32_t da = smb + OFF_VT + (dc * 4) * PB + p * 4;
            asm volatile("st.shared.b32 [%0], %1;" :: "r"(da),          "r"(x));
            asm volatile("st.shared.b32 [%0], %1;" :: "r"(da + PB),     "r"(y));
            asm volatile("st.shared.b32 [%0], %1;" :: "r"(da + 2 * PB), "r"(z));
            asm volatile("st.shared.b32 [%0], %1;" :: "r"(da + 3 * PB), "r"(t));
        }
    };

    // prologue: V(0), K(0), K(1)
    issue_v(0);
    issue_k(0, 0);
    issue_k(1, 1);

    // ================= bit-packed mask: 128 rows x 2048 bits =================
    for (int base = 0; base < 8192; base += 64) {
        const int w0idx = base + w * 8;
        int vals[8];
#pragma unroll
        for (int j = 0; j < 8; ++j) {
            const int widx = w0idx + j;
            vals[j] = Mg[(size_t)(q0 + (widx >> 6)) * SLEN + (widx & 63) * 32 + l];
        }
#pragma unroll
        for (int j = 0; j < 8; ++j) {
            const unsigned bal = __ballot_sync(0xffffffffu, vals[j] != 0);
            const int widx = w0idx + j;
            if (l == 0) BMw[(widx >> 6) * BM_STRIDE + (widx & 63)] = bal;
        }
    }

    // ---- Q A-fragments (tf32); slots for s=2t+h take d = t*16 + (l&3)*4 + 2h + {0,1} ----
    const int rl0 = w * 16 + (l >> 2);
    const int r0  = q0 + rl0;
    uint32_t qa[8][4];
    {
        const float* Qr0 = Qg + (size_t)r0 * DHEAD;
#pragma unroll
        for (int s = 0; s < 8; ++s) {
            const int d0 = (s >> 1) * 16 + (l & 3) * 4 + (s & 1) * 2;
            qa[s][0] = f2tf(Qr0[d0]);
            qa[s][1] = f2tf(Qr0[8 * DHEAD + d0]);
            qa[s][2] = f2tf(Qr0[d0 + 1]);
            qa[s][3] = f2tf(Qr0[8 * DHEAD + d0 + 1]);
        }
    }

    // per-lane LDS.128 base offset (same formula for K and VT tiles)
    const uint32_t laneB = (uint32_t)((l >> 2) * PB + (l & 3) * 16);
    const int j0 = (l & 3) * 2;

    float oacc[8][4];
#pragma unroll
    for (int nb = 0; nb < 8; ++nb) { oacc[nb][0]=0.f; oacc[nb][1]=0.f; oacc[nb][2]=0.f; oacc[nb][3]=0.f; }
    float rs0 = 0.f, rs1 = 0.f;

    // ============================ PASS 1: rowsums + O ============================
    for (int kt = 0; kt < NKT; ++kt) {
        const int b = kt & 1;

        asm volatile("cp.async.wait_group 1;" ::: "memory");   // K(kt), V(kt) ready
        __syncthreads();

        transpose_v();
        sweep_k(b);
        __syncthreads();

        issue_v(kt + 1);      // VS free now

        // ---- S = Q K^T (one LDS.128 feeds two MMAs) ----
        float sacc[8][4];
#pragma unroll
        for (int nb = 0; nb < 8; ++nb) { sacc[nb][0]=0.f; sacc[nb][1]=0.f; sacc[nb][2]=0.f; sacc[nb][3]=0.f; }
        const uint32_t aK = smb + OFF_K0 + b * KBUF + laneB;
#pragma unroll
        for (int t = 0; t < 4; ++t) {
#pragma unroll
            for (int nb = 0; nb < 8; ++nb) {
                uint32_t w0, w1, w2, w3;
                lds128(w0, w1, w2, w3, aK + nb * (8 * PB) + t * 64);
                mma_tf32(sacc[nb], qa[2 * t],     w0, w1);
                mma_tf32(sacc[nb], qa[2 * t + 1], w2, w3);
            }
        }

        // ---- mask bits, exp, rowsum, P->A frags ({c0,c2,c1,c3}) ----
        uint64_t bits0, bits1;
        {
            uint2 b0v = *(const uint2*)(BMw + rl0 * BM_STRIDE + kt * 2);
            uint2 b1v = *(const uint2*)(BMw + (rl0 + 8) * BM_STRIDE + kt * 2);
            bits0 = ((uint64_t)b0v.y << 32 | b0v.x) >> j0;
            bits1 = ((uint64_t)b1v.y << 32 | b1v.x) >> j0;
        }
        uint32_t pp[8][4];
#pragma unroll
        for (int nb = 0; nb < 8; ++nb) {
            const uint32_t s0 = (uint32_t)(bits0 >> (nb * 8));
            const uint32_t s1 = (uint32_t)(bits1 >> (nb * 8));
            float p0 = (s0 & 1) ? __expf(sacc[nb][0] * 0.125f) : 0.f;
            float p1 = (s0 & 2) ? __expf(sacc[nb][1] * 0.125f) : 0.f;
            float p2 = (s1 & 1) ? __expf(sacc[nb][2] * 0.125f) : 0.f;
            float p3 = (s1 & 2) ? __expf(sacc[nb][3] * 0.125f) : 0.f;
            rs0 += p0 + p1;
            rs1 += p2 + p3;
            pp[nb][0] = f2tf(p0);
            pp[nb][1] = f2tf(p2);
            pp[nb][2] = f2tf(p1);
            pp[nb][3] = f2tf(p3);
        }

        // ---- O += P V (VT pre-shuffled; one LDS.128 feeds two MMAs) ----
        const uint32_t aV = smb + OFF_VT + laneB;
#pragma unroll
        for (int t = 0; t < 4; ++t) {
#pragma unroll
            for (int nb = 0; nb < 8; ++nb) {
                uint32_t w0, w1, w2, w3;
                lds128(w0, w1, w2, w3, aV + nb * (8 * PB) + t * 64);
                mma_tf32(oacc[nb], pp[2 * t],     w0, w1);
                mma_tf32(oacc[nb], pp[2 * t + 1], w2, w3);
            }
        }

        __syncthreads();
        issue_k(kt + 2, b);
    }

    // ---- row sums: reduce 4 lanes per row, invert ----
    rs0 += __shfl_xor_sync(0xffffffffu, rs0, 1);
    rs0 += __shfl_xor_sync(0xffffffffu, rs0, 2);
    rs1 += __shfl_xor_sync(0xffffffffu, rs1, 1);
    rs1 += __shfl_xor_sync(0xffffffffu, rs1, 2);
    if ((l & 3) == 0) {
        rowsum[rl0]     = rs0;
        rowsum[rl0 + 8] = rs1;
    }
    __syncthreads();
    if (tid < TQ) rowsum[tid] = 1.0f / rowsum[tid];
    __syncthreads();

    const float inv0 = rowsum[rl0];
    const float inv1 = rowsum[rl0 + 8];

    // ---- write normalized O ----
    {
        float* or0 = Og + (size_t)r0 * DHEAD + (l & 3) * 2;
        float* or8 = or0 + 8 * DHEAD;
#pragma unroll
        for (int nb = 0; nb < 8; ++nb) {
            *(float2*)(or0 + nb * 8) = make_float2(oacc[nb][0] * inv0, oacc[nb][1] * inv0);
            *(float2*)(or8 + nb * 8) = make_float2(oacc[nb][2] * inv1, oacc[nb][3] * inv1);
        }
    }
    __syncthreads();

    // ============================ PASS 2: normalized attention ============================
    issue_k(0, 0);
    issue_k(1, 1);

    float* ab0 = Ag + (size_t)r0 * SLEN + (l & 3) * 2;

    for (int kt = 0; kt < NKT; ++kt) {
        const int b = kt & 1;

        asm volatile("cp.async.wait_group 1;" ::: "memory");
        __syncthreads();
        sweep_k(b);
        __syncthreads();

        // ---- S recompute (LDS.128 paired MMAs) ----
        float sacc[8][4];
#pragma unroll
        for (int nb = 0; nb < 8; ++nb) { sacc[nb][0]=0.f; sacc[nb][1]=0.f; sacc[nb][2]=0.f; sacc[nb][3]=0.f; }
        const uint32_t aK = smb + OFF_K0 + b * KBUF + laneB;
#pragma unroll
        for (int t = 0; t < 4; ++t) {
#pragma unroll
            for (int nb = 0; nb < 8; ++nb) {
                uint32_t w0, w1, w2, w3;
                lds128(w0, w1, w2, w3, aK + nb * (8 * PB) + t * 64);
                mma_tf32(sacc[nb], qa[2 * t],     w0, w1);
                mma_tf32(sacc[nb], qa[2 * t + 1], w2, w3);
            }
        }

        // ---- exp * inv, write normalized attention once ----
        uint64_t bits0, bits1;
        {
            uint2 b0v = *(const uint2*)(BMw + rl0 * BM_STRIDE + kt * 2);
            uint2 b1v = *(const uint2*)(BMw + (rl0 + 8) * BM_STRIDE + kt * 2);
            bits0 = ((uint64_t)b0v.y << 32 | b0v.x) >> j0;
            bits1 = ((uint64_t)b1v.y << 32 | b1v.x) >> j0;
        }
        float* ar0 = ab0 + kt * TK;
        float* ar8 = ar0 + 8 * SLEN;
#pragma unroll
        for (int nb = 0; nb < 8; ++nb) {
            const uint32_t s0 = (uint32_t)(bits0 >> (nb * 8));
            const uint32_t s1 = (uint32_t)(bits1 >> (nb * 8));
            float p0 = (s0 & 1) ? __expf(sacc[nb][0] * 0.125f) * inv0 : 0.f;
            float p1 = (s0 & 2) ? __expf(sacc[nb][1] * 0.125f) * inv0 : 0.f;
            float p2 = (s1 & 1) ? __expf(sacc[nb][2] * 0.125f) * inv1 : 0.f;
            float p3 = (s1 & 2) ? __expf(sacc[nb][3] * 0.125f) * inv1 : 0.f;
            *(float2*)(ar0 + nb * 8) = make_float2(p0, p1);
            *(float2*)(ar8 + nb * 8) = make_float2(p2, p3);
        }

        __syncthreads();
        issue_k(kt + 2, b);
    }
}

extern "C" void kernel_launch(void* const* d_in, const int* in_sizes, int n_in,
                              void* d_out, int out_size)
{
    const float* Q    = (const float*)d_in[0];
    const float* K    = (const float*)d_in[1];
    const float* V    = (const float*)d_in[2];
    const int*   mask = (const int*)d_in[3];
    (void)in_sizes; (void)n_in; (void)out_size;

    float* out  = (float*)d_out;
    float* attn = out + OUT_ELEMS;

    static int configured = 0;
    if (!configured) {
        cudaFuncSetAttribute(sdpa_tf32_kernel,
                             cudaFuncAttributeMaxDynamicSharedMemorySize, SMEM_BYTES);
        configured = 1;
    }

    dim3 grid(SLEN / TQ, BHN);   // (16, 64)
    sdpa_tf32_kernel<<<grid, NTHREADS, SMEM_BYTES>>>(Q, K, V, mask, out, attn);
}